// round 4
// baseline (speedup 1.0000x reference)
#include <cuda_runtime.h>
#include <math.h>

// ---------------------------------------------------------------------------
// B=256, L=256, V=14, EMB=512, pooled length NH=128, NPAIR = C(14,2)+14 = 105
// ---------------------------------------------------------------------------
#define NPAIR 105
typedef unsigned long long ull;

// ---------------------------------------------------------------------------
// Scratch (__device__ globals; no runtime allocation)
// ---------------------------------------------------------------------------
__device__ __align__(16) float g_cwT[2][512 * 768];        // [br][i*768 + kh*256 + o]
__device__ __align__(16) float g_pp[2][NPAIR * 512];       // pooled pair embeddings
__device__ __align__(16) float g_CpP[8][2][NPAIR * 768];   // K-split partials
__device__ __align__(16) float g_Cp[2][NPAIR * 768];       // Cpair[p][kh*256+o]
__device__ __align__(16) float g_E[2][NPAIR * 128 * 128];  // E[p][h][j]
__device__ float            g_bpart[2][128 * 128];         // bias partials per hp
__device__ int              g_pIdx[256 * 128];             // friend pair idx per (b,h)
__device__ float            g_eout[256 * 128];             // enemy softmax output
__device__ float            g_W[3 * 64 * 128];             // manip conv weight sums
__device__ float            g_A[3 * 64 * 256];             // manip lin reduced

__device__ __forceinline__ int pair_idx(int a, int b) {
    int lo = a < b ? a : b;
    int hi = a < b ? b : a;
    return lo * 14 - (lo * (lo - 1)) / 2 + (hi - lo);
}
__device__ __forceinline__ ull splat2(float x) {
    unsigned u = __float_as_uint(x);
    return (ull)u | ((ull)u << 32);
}
__device__ __forceinline__ float2 unpack2(ull v) {
    float2 r;
    r.x = __uint_as_float((unsigned)v);
    r.y = __uint_as_float((unsigned)(v >> 32));
    return r;
}
__device__ __forceinline__ unsigned smem_u32(const void* p) {
    return (unsigned)__cvta_generic_to_shared(p);
}

// ---------------------------------------------------------------------------
// 1. Fused prep: cwT transpose, pooled pairs, manip wsum, manip areduce.
//    grid.x = 512 (cwT) + 210 (pp) + 96 (wsum) + 64 (areduce) = 882, 256 thr.
// ---------------------------------------------------------------------------
__global__ void k_prep1(const float* __restrict__ ecw, const float* __restrict__ fcw,
                        const float* __restrict__ eemb, const float* __restrict__ femb,
                        const float* __restrict__ mcw, const float* __restrict__ mlw) {
    __shared__ float s[4608];
    int bid = blockIdx.x;
    int t = threadIdx.x;
    if (bid < 512) {
        // cwT: cwT[i*768 + kh*256 + o] = cw[o,i,kh,1]
        int br = bid >> 8, o = bid & 255;
        const float* src = (br ? fcw : ecw) + o * 4608;
#pragma unroll
        for (int r = 0; r < 18; r++) s[t + r * 256] = src[t + r * 256];
        __syncthreads();
        float* dst = g_cwT[br];
#pragma unroll
        for (int r = 0; r < 6; r++) {
            int v = t + r * 256;
            int i = v / 3, kh = v - i * 3;
            dst[i * 768 + kh * 256 + o] = s[i * 9 + kh * 3 + 1];
        }
    } else if (bid < 722) {
        // pp
        int idx = bid - 512;
        int br = idx / NPAIR, p = idx % NPAIR;
        const float* emb = br ? femb : eemb;
        int t1 = 0, rem = p;
        while (rem >= 14 - t1) { rem -= 14 - t1; t1++; }
        int t2 = t1 + rem;
        g_pp[br][p * 512 + t]       = fmaxf(emb[t1 * 512 + t],       emb[t2 * 512 + t]);
        g_pp[br][p * 512 + t + 256] = fmaxf(emb[t1 * 512 + t + 256], emb[t2 * 512 + t + 256]);
    } else if (bid < 818) {
        // wsum
        int tid = (bid - 722) * 256 + t;
        int v = tid / 8192, r = tid & 8191, o = r >> 7, i = r & 127;
        int base = ((o * 128 + i) * 3) * 3 + 1;
        float w0 = mcw[base], w1 = mcw[base + 3], w2 = mcw[base + 6];
        float sv = (v == 0) ? (w1 + w2) : (v == 1 ? (w0 + w1 + w2) : (w0 + w1));
        g_W[tid] = sv;
    } else {
        // areduce
        int o = bid - 818, j = t;
        const float* base = mlw + (o << 7) * 256 + j;
        float a0 = base[0];
        float ae = base[127 * 256];
        float ai = 0.f;
#pragma unroll 16
        for (int h = 1; h < 127; h++) ai += base[h * 256];
        g_A[0 * 16384 + o * 256 + j] = a0;
        g_A[1 * 16384 + o * 256 + j] = ai;
        g_A[2 * 16384 + o * 256 + j] = ae;
    }
}

// ---------------------------------------------------------------------------
// 2a. Cpair partials: 7 pairs per block, K split into 8 chunks of 64.
//     grid (15, 2, 8), 768 thr.
// ---------------------------------------------------------------------------
__global__ void __launch_bounds__(768) k_cpair_ks() {
    __shared__ float s[7][64];
    int br = blockIdx.y, q = blockIdx.z;
    int p0 = blockIdx.x * 7;
    int t = threadIdx.x;
    if (t < 448) {
        int pl = t >> 6, ii = t & 63;
        s[pl][ii] = g_pp[br][(p0 + pl) * 512 + q * 64 + ii];
    }
    __syncthreads();
    const float* ct = g_cwT[br] + (q * 64) * 768 + t;
    float a[7];
#pragma unroll
    for (int pl = 0; pl < 7; pl++) a[pl] = 0.f;
#pragma unroll 8
    for (int i = 0; i < 64; i++) {
        float w = ct[i * 768];
#pragma unroll
        for (int pl = 0; pl < 7; pl++) a[pl] += s[pl][i] * w;
    }
#pragma unroll
    for (int pl = 0; pl < 7; pl++)
        g_CpP[q][br][(p0 + pl) * 768 + t] = a[pl];
}

// 2b. Reduce the 8 partials.
__global__ void k_cpair_red() {
    int br = blockIdx.y, p = blockIdx.x, c = threadIdx.x;
    int idx = p * 768 + c;
    float s0 = g_CpP[0][br][idx] + g_CpP[1][br][idx];
    float s1 = g_CpP[2][br][idx] + g_CpP[3][br][idx];
    float s2 = g_CpP[4][br][idx] + g_CpP[5][br][idx];
    float s3 = g_CpP[6][br][idx] + g_CpP[7][br][idx];
    g_Cp[br][idx] = (s0 + s1) + (s2 + s3);
}

// ---------------------------------------------------------------------------
// 3. E-table SGEMM + bias partials.  fp32x2 FFMA, pre-splatted A (single buf),
//    cp.async double-buffered B, register-prefetched A.
//    grid = (128 h', 2 br), 256 thr, 8p x 8j microtile, BK=16, K=768.
//    Bias: tiles k0 in [256,512) hold lin[(o,hp)] rows (kh=1) ->
//    g_bpart[br][hp*128+j] = sum_o cb[o]*lin[(o,hp)][j].
// ---------------------------------------------------------------------------
__global__ void __launch_bounds__(256, 2) k_egemm(const float* __restrict__ elw,
                                                  const float* __restrict__ flw,
                                                  const float* __restrict__ ecb,
                                                  const float* __restrict__ fcb) {
    const int hp = blockIdx.x;
    const int br = blockIdx.y;
    const float* lin = br ? flw : elw;
    const float* cb  = br ? fcb : ecb;
    const float* Cp = g_Cp[br];

    __shared__ __align__(16) ull   As2[16][132];     // splatted A (single buffer)
    __shared__ __align__(16) float Bs[2][16][132];   // double-buffered B
    __shared__ float scb[256];
    __shared__ float sb[256];

    const int t = threadIdx.x, tx = t & 15, ty = t >> 4;
    // A prefetch geometry: slot0 p0=t>>2 (<64), slot1 p1=64+(t>>2); kq=(t&3)*4
    const int pA0 = t >> 2;
    const int pA1 = 64 + pA0;
    const int kqA = (t & 3) << 2;
    // B fill geometry (2 slots)
    const int krB0 = t >> 5,        jqB0 = (t & 31) << 2;
    const int krB1 = (t + 256) >> 5, jqB1 = jqB0;

    ull acc2[8][4];
#pragma unroll
    for (int i = 0; i < 8; i++)
#pragma unroll
        for (int q = 0; q < 4; q++) acc2[i][q] = 0ull;
    float bias_acc = 0.f;

    scb[t] = cb[t];

    unsigned sBs = smem_u32(&Bs[0][0][0]);

    // ---- prologue: tile 0 ----
    float4 aP0 = *(const float4*)(Cp + pA0 * 768 + kqA);
    float4 aP1 = (pA1 < NPAIR) ? *(const float4*)(Cp + pA1 * 768 + kqA)
                               : make_float4(0.f, 0.f, 0.f, 0.f);
    {
        // B tile 0 (k0=0 -> kh=0, h=hp+1)
        int h = hp + 1;
        int ok = (h < 128) ? 1 : 0;
#pragma unroll
        for (int sL = 0; sL < 2; sL++) {
            int kr = sL ? krB1 : krB0;
            int jq = sL ? jqB1 : jqB0;
            int o = kr;  // k0=0: k=kr, kh=0, o=kr... (kr<16 so o=kr)
            const float* gsrc = lin + (ok ? (((o << 7) + h) * 128 + jq) : 0);
            unsigned sa = sBs + (unsigned)((0 * (16 * 132) + kr * 132 + jq) * 4);
            int ssz = ok ? 16 : 0;
            asm volatile("cp.async.cg.shared.global [%0], [%1], 16, %2;"
                         :: "r"(sa), "l"(gsrc), "r"(ssz));
        }
        asm volatile("cp.async.commit_group;");
    }
    As2[kqA + 0][pA0] = splat2(aP0.x);
    As2[kqA + 1][pA0] = splat2(aP0.y);
    As2[kqA + 2][pA0] = splat2(aP0.z);
    As2[kqA + 3][pA0] = splat2(aP0.w);
    As2[kqA + 0][pA1] = splat2(aP1.x);
    As2[kqA + 1][pA1] = splat2(aP1.y);
    As2[kqA + 2][pA1] = splat2(aP1.z);
    As2[kqA + 3][pA1] = splat2(aP1.w);
    asm volatile("cp.async.wait_group 0;");
    __syncthreads();

    int buf = 0;
    for (int tile = 0; tile < 48; tile++) {
        int k0 = tile << 4;
        // ---- prefetch next tile ----
        if (tile < 47) {
            int kn = k0 + 16;
            aP0 = *(const float4*)(Cp + pA0 * 768 + kn + kqA);
            aP1 = (pA1 < NPAIR) ? *(const float4*)(Cp + pA1 * 768 + kn + kqA)
                                : make_float4(0.f, 0.f, 0.f, 0.f);
#pragma unroll
            for (int sL = 0; sL < 2; sL++) {
                int kr = sL ? krB1 : krB0;
                int jq = sL ? jqB1 : jqB0;
                int k = kn + kr;
                int kh = k >> 8, o = k & 255;
                int h = hp + 1 - kh;
                int ok = ((unsigned)h < 128u) ? 1 : 0;
                const float* gsrc = lin + (ok ? (((o << 7) + h) * 128 + jq) : 0);
                unsigned sa = sBs + (unsigned)((((buf ^ 1) * 16 + kr) * 132 + jq) * 4);
                int ssz = ok ? 16 : 0;
                asm volatile("cp.async.cg.shared.global [%0], [%1], 16, %2;"
                             :: "r"(sa), "l"(gsrc), "r"(ssz));
            }
            asm volatile("cp.async.commit_group;");
        }
        // ---- compute ----
#pragma unroll
        for (int kk = 0; kk < 16; kk++) {
            const ull* ar = &As2[kk][ty * 8];
            ulonglong2 a01 = *(const ulonglong2*)(ar + 0);
            ulonglong2 a23 = *(const ulonglong2*)(ar + 2);
            ulonglong2 a45 = *(const ulonglong2*)(ar + 4);
            ulonglong2 a67 = *(const ulonglong2*)(ar + 6);
            ulonglong2 u0 = *(const ulonglong2*)&Bs[buf][kk][tx * 8];
            ulonglong2 u1 = *(const ulonglong2*)&Bs[buf][kk][tx * 8 + 4];
            ull a2[8] = {a01.x, a01.y, a23.x, a23.y, a45.x, a45.y, a67.x, a67.y};
            ull b2[4] = {u0.x, u0.y, u1.x, u1.y};
#pragma unroll
            for (int i = 0; i < 8; i++)
#pragma unroll
                for (int q = 0; q < 4; q++)
                    asm("fma.rn.f32x2 %0, %1, %2, %0;"
                        : "+l"(acc2[i][q]) : "l"(a2[i]), "l"(b2[q]));
        }
        // ---- bias partial from kh=1 tiles ----
        if ((unsigned)(k0 - 256) < 256u) {
            int jj = t & 127, hf = t >> 7;
#pragma unroll
            for (int r = 0; r < 8; r++) {
                int kr = hf * 8 + r;
                int o = (k0 + kr) & 255;
                bias_acc += scb[o] * Bs[buf][kr][jj];
            }
        }
        __syncthreads();  // everyone done with As2 / Bs[buf]
        if (tile < 47) {
            As2[kqA + 0][pA0] = splat2(aP0.x);
            As2[kqA + 1][pA0] = splat2(aP0.y);
            As2[kqA + 2][pA0] = splat2(aP0.z);
            As2[kqA + 3][pA0] = splat2(aP0.w);
            As2[kqA + 0][pA1] = splat2(aP1.x);
            As2[kqA + 1][pA1] = splat2(aP1.y);
            As2[kqA + 2][pA1] = splat2(aP1.z);
            As2[kqA + 3][pA1] = splat2(aP1.w);
            asm volatile("cp.async.wait_group 0;");
            __syncthreads();
            buf ^= 1;
        }
    }

    // ---- store E ----
    float* E = g_E[br];
#pragma unroll
    for (int i = 0; i < 8; i++) {
        int p = ty * 8 + i;
        if (p < NPAIR) {
            float* dst = E + ((p << 7) + hp) * 128 + tx * 8;
            float2 v0 = unpack2(acc2[i][0]);
            float2 v1 = unpack2(acc2[i][1]);
            float2 v2 = unpack2(acc2[i][2]);
            float2 v3 = unpack2(acc2[i][3]);
            *(float4*)dst       = make_float4(v0.x, v0.y, v1.x, v1.y);
            *(float4*)(dst + 4) = make_float4(v2.x, v2.y, v3.x, v3.y);
        }
    }
    // ---- store bias partial ----
    __syncthreads();
    sb[t] = bias_acc;
    __syncthreads();
    if (t < 128) g_bpart[br][hp * 128 + t] = sb[t] + sb[t + 128];
}

// ---------------------------------------------------------------------------
// 4. Enemy gather + softmax (bias = sum of per-hp partials, L2-hot)
// ---------------------------------------------------------------------------
__global__ void k_gatherE(const int* __restrict__ x, const float* __restrict__ linb) {
    int b = blockIdx.x, j = threadIdx.x;
    __shared__ int sp[128];
    __shared__ float red[128];
    sp[j] = pair_idx(x[b * 256 + 2 * j], x[b * 256 + 2 * j + 1]);
    __syncthreads();
    float acc = linb[j];
#pragma unroll 8
    for (int hp = 0; hp < 128; hp++) acc += g_bpart[0][hp * 128 + j];
    const float* E = g_E[0];
#pragma unroll 8
    for (int h = 0; h < 128; h++) acc += E[((sp[h] << 7) + h) * 128 + j];

    red[j] = acc;
    __syncthreads();
    for (int s = 64; s > 0; s >>= 1) {
        if (j < s) red[j] = fmaxf(red[j], red[j + s]);
        __syncthreads();
    }
    float m = red[0];
    __syncthreads();
    float e = expf(acc - m);
    red[j] = e;
    __syncthreads();
    for (int s = 64; s > 0; s >>= 1) {
        if (j < s) red[j] += red[j + s];
        __syncthreads();
    }
    g_eout[b * 128 + j] = e / red[0];
}

// ---------------------------------------------------------------------------
// 5. Manipulator main + friend token/pair generation (2 batches per block)
// ---------------------------------------------------------------------------
__global__ void k_manip(const float* __restrict__ mb, const float* __restrict__ mlb) {
    int b0 = blockIdx.x * 2;
    int t = threadIdx.x;  // 256
    __shared__ float eo[2][128];
    __shared__ float ry[2][192];
    __shared__ int tok[2][256];
    eo[t >> 7][t & 127] = g_eout[(b0 + (t >> 7)) * 128 + (t & 127)];
    __syncthreads();
    if (t < 192) {
        int v = t >> 6, o = t & 63;
        const float* W = g_W + v * 8192 + o * 128;
        float base = mb[o];
        float s0 = base, s1 = base;
#pragma unroll 4
        for (int i = 0; i < 128; i++) {
            float w = W[i];
            s0 += eo[0][i] * w;
            s1 += eo[1][i] * w;
        }
        ry[0][t] = fmaxf(s0, 0.f);
        ry[1][t] = fmaxf(s1, 0.f);
    }
    __syncthreads();
    int j = t;
    float base = mlb[j];
    float acc0 = base, acc1 = base;
#pragma unroll 2
    for (int o = 0; o < 64; o++) {
        float a0 = g_A[o * 256 + j];
        float a1 = g_A[16384 + o * 256 + j];
        float a2 = g_A[32768 + o * 256 + j];
        acc0 += ry[0][o] * a0 + ry[0][64 + o] * a1 + ry[0][128 + o] * a2;
        acc1 += ry[1][o] * a0 + ry[1][64 + o] * a1 + ry[1][128 + o] * a2;
    }
    tok[0][j] = (int)(((long long)floorf(fabsf(acc0) * 100.0f)) % 14);
    tok[1][j] = (int)(((long long)floorf(fabsf(acc1) * 100.0f)) % 14);
    __syncthreads();
    {
        int bb = t >> 7, h = t & 127;
        g_pIdx[(b0 + bb) * 128 + h] = pair_idx(tok[bb][2 * h], tok[bb][2 * h + 1]);
    }
}

// ---------------------------------------------------------------------------
// 6. Friend gather + head + softmax(14)
// ---------------------------------------------------------------------------
__global__ void k_gatherF_head(const float* __restrict__ flb,
                               const float* __restrict__ L2,
                               const float* __restrict__ b2,
                               float* __restrict__ out) {
    int b = blockIdx.x, j = threadIdx.x;
    __shared__ int sp[128];
    __shared__ float f[128];
    sp[j] = g_pIdx[b * 128 + j];
    __syncthreads();
    float acc = flb[j];
#pragma unroll 8
    for (int hp = 0; hp < 128; hp++) acc += g_bpart[1][hp * 128 + j];
    const float* E = g_E[1];
#pragma unroll 8
    for (int h = 0; h < 128; h++) acc += E[((sp[h] << 7) + h) * 128 + j];
    f[j] = acc;
    __syncthreads();
    if (j < 32) {
        float a = -INFINITY;
        if (j < 14) {
            a = b2[j];
#pragma unroll 4
            for (int i = 0; i < 128; i++) a += f[i] * L2[i * 14 + j];
        }
        float m = a;
        for (int off = 16; off; off >>= 1) m = fmaxf(m, __shfl_xor_sync(0xffffffffu, m, off));
        float e = (j < 14) ? expf(a - m) : 0.f;
        float s = e;
        for (int off = 16; off; off >>= 1) s += __shfl_xor_sync(0xffffffffu, s, off);
        if (j < 14) out[b * 14 + j] = e / s;
    }
}

// ---------------------------------------------------------------------------
// Launch sequence (single stream, graph-capturable)
// ---------------------------------------------------------------------------
extern "C" void kernel_launch(void* const* d_in, const int* in_sizes, int n_in,
                              void* d_out, int out_size) {
    (void)in_sizes; (void)n_in; (void)out_size;
    const int*   x    = (const int*)  d_in[0];
    const float* eemb = (const float*)d_in[1];
    const float* ecw  = (const float*)d_in[2];
    const float* ecb  = (const float*)d_in[3];
    const float* elw  = (const float*)d_in[4];
    const float* elb  = (const float*)d_in[5];
    // d_in[6] = rand_proj: dead (fog_of_war perm == arange)
    const float* mcw  = (const float*)d_in[7];
    const float* mcb  = (const float*)d_in[8];
    const float* mlw  = (const float*)d_in[9];
    const float* mlb  = (const float*)d_in[10];
    const float* femb = (const float*)d_in[11];
    const float* fcw  = (const float*)d_in[12];
    const float* fcb  = (const float*)d_in[13];
    const float* flw  = (const float*)d_in[14];
    const float* flb  = (const float*)d_in[15];
    const float* fl2w = (const float*)d_in[16];
    const float* fl2b = (const float*)d_in[17];
    float* out = (float*)d_out;

    k_prep1    <<<882, 256>>>(ecw, fcw, eemb, femb, mcw, mlw);
    k_cpair_ks <<<dim3(15, 2, 8), 768>>>();
    k_cpair_red<<<dim3(NPAIR, 2), 768>>>();

    // Both branches' E tables (+ bias partials) in one launch
    k_egemm <<<dim3(128, 2), 256>>>(elw, flw, ecb, fcb);

    k_gatherE<<<256, 128>>>(x, elb);
    k_manip  <<<128, 256>>>(mcb, mlb);
    k_gatherF_head<<<256, 128>>>(flb, fl2w, fl2b, out);
}